// round 4
// baseline (speedup 1.0000x reference)
#include <cuda_runtime.h>
#include <mma.h>
#include <math.h>
#include <cstdint>

using namespace nvcuda;

#define Nn 50000
#define Ee 500000
#define Tt 8
#define Rr 8
#define NT 391                 // ceil(50000/128) row tiles
#define NP (NT*128)            // padded rows = 50048

// smem plane layout (floats)
#define AH_LD 68               // 64-wide K chunk + pad
#define BH_LD 132              // 128 cols + pad
#define SM_AH (128*AH_LD)      // 8704
#define SM_BH (64*BH_LD)       // 8448
// [Ah | Al | Bh | Bl]
#define OFF_AH 0
#define OFF_AL (SM_AH)
#define OFF_BH (2*SM_AH)
#define OFF_BL (2*SM_AH + SM_BH)
#define GEMM_SMEM ((2*SM_AH + 2*SM_BH)*4)   // 137216 B

// ---------------- device scratch ----------------
__device__ float g_k[(size_t)NP*128];
__device__ float g_q[(size_t)Nn*128];
__device__ float g_v[(size_t)NP*128];
__device__ float g_kA[(size_t)Rr*NP*128];
__device__ float g_vM[(size_t)Rr*NP*128];
__device__ float g_score[Ee];
__device__ float g_ex[Ee];
__device__ unsigned g_segmax[Nn*Rr];
__device__ float g_denom[Nn*Rr];
__device__ float g_agg[(size_t)Nn*128];
__device__ int g_bucket[Nn];
__device__ int g_cnt[Tt];
__device__ int g_off[Tt+1];
__device__ int g_cursor[Tt];

// ---------------- helpers ----------------
__device__ __forceinline__ float to_tf32(float x){
    float r;
    asm("cvt.rna.tf32.f32 %0, %1;" : "=f"(r) : "f"(x));
    return r;
}
__device__ __forceinline__ unsigned ford(float f){
    unsigned u = __float_as_uint(f);
    return (u & 0x80000000u) ? ~u : (u | 0x80000000u);
}
__device__ __forceinline__ float ordf(unsigned u){
    return (u & 0x80000000u) ? __uint_as_float(u & 0x7fffffffu) : __uint_as_float(~u);
}

typedef wmma::fragment<wmma::matrix_a, 16, 16, 8, wmma::precision::tf32, wmma::row_major> FragA;
typedef wmma::fragment<wmma::matrix_b, 16, 16, 8, wmma::precision::tf32, wmma::row_major> FragB;
typedef wmma::fragment<wmma::accumulator, 16, 16, 8, float> FragC;

__device__ __forceinline__ void split4(float4 v, float4& hi, float4& lo){
    hi.x = to_tf32(v.x); lo.x = to_tf32(v.x - hi.x);
    hi.y = to_tf32(v.y); lo.y = to_tf32(v.y - hi.y);
    hi.z = to_tf32(v.z); lo.z = to_tf32(v.z - hi.z);
    hi.w = to_tf32(v.w); lo.w = to_tf32(v.w - hi.w);
}

// stage 128-row x 64-col A chunk (gathered rows), split into hi/lo planes
__device__ __forceinline__ void stage_A_gather(float* sm, const float* __restrict__ X,
                                               const int* rows_s, int mc, int ch, int tid){
    #pragma unroll
    for (int i = 0; i < 8; i++){
        int idx = tid + i*256;           // 0..2047
        int m = idx >> 4, c4 = idx & 15; // 128 rows x 16 float4
        float4 v = make_float4(0.f,0.f,0.f,0.f);
        if (m < mc) v = *reinterpret_cast<const float4*>(X + (size_t)rows_s[m]*128 + ch*64 + c4*4);
        float4 hi, lo; split4(v, hi, lo);
        *reinterpret_cast<float4*>(sm + OFF_AH + m*AH_LD + c4*4) = hi;
        *reinterpret_cast<float4*>(sm + OFF_AL + m*AH_LD + c4*4) = lo;
    }
}
// linear-row version (padded input)
__device__ __forceinline__ void stage_A_linear(float* sm, const float* __restrict__ X,
                                               int row0, int ch, int tid){
    #pragma unroll
    for (int i = 0; i < 8; i++){
        int idx = tid + i*256;
        int m = idx >> 4, c4 = idx & 15;
        float4 v = *reinterpret_cast<const float4*>(X + (size_t)(row0 + m)*128 + ch*64 + c4*4);
        float4 hi, lo; split4(v, hi, lo);
        *reinterpret_cast<float4*>(sm + OFF_AH + m*AH_LD + c4*4) = hi;
        *reinterpret_cast<float4*>(sm + OFF_AL + m*AH_LD + c4*4) = lo;
    }
}
// stage 64-row x 128-col B chunk (W rows ch*64..+64), split
__device__ __forceinline__ void stage_B_split(float* sm, const float* __restrict__ W,
                                              int ch, int tid){
    #pragma unroll
    for (int i = 0; i < 8; i++){
        int idx = tid + i*256;           // 0..2047
        int row = idx >> 5, c4 = idx & 31;
        float4 v = *reinterpret_cast<const float4*>(W + (size_t)(ch*64 + row)*128 + c4*4);
        float4 hi, lo; split4(v, hi, lo);
        *reinterpret_cast<float4*>(sm + OFF_BH + row*BH_LD + c4*4) = hi;
        *reinterpret_cast<float4*>(sm + OFF_BL + row*BH_LD + c4*4) = lo;
    }
}

// 3xTF32 MMA over one 64-wide K chunk.
// warp tiling: wr = wid>>1 (0..3) -> rows wr*32 (2 frags), wc = wid&1 -> cols wc*64 (4 frags)
__device__ __forceinline__ void mma_chunk(const float* sm, FragC cf[2][4], int wr, int wc){
    #pragma unroll
    for (int kk = 0; kk < 64; kk += 8){
        FragA ah0, ah1, al0, al1;
        wmma::load_matrix_sync(ah0, sm + OFF_AH + (wr*32+ 0)*AH_LD + kk, AH_LD);
        wmma::load_matrix_sync(ah1, sm + OFF_AH + (wr*32+16)*AH_LD + kk, AH_LD);
        wmma::load_matrix_sync(al0, sm + OFF_AL + (wr*32+ 0)*AH_LD + kk, AH_LD);
        wmma::load_matrix_sync(al1, sm + OFF_AL + (wr*32+16)*AH_LD + kk, AH_LD);
        #pragma unroll
        for (int nt = 0; nt < 4; nt++){
            FragB bh, bl;
            wmma::load_matrix_sync(bh, sm + OFF_BH + kk*BH_LD + wc*64 + nt*16, BH_LD);
            wmma::load_matrix_sync(bl, sm + OFF_BL + kk*BH_LD + wc*64 + nt*16, BH_LD);
            wmma::mma_sync(cf[0][nt], ah0, bh, cf[0][nt]);
            wmma::mma_sync(cf[0][nt], ah0, bl, cf[0][nt]);
            wmma::mma_sync(cf[0][nt], al0, bh, cf[0][nt]);
            wmma::mma_sync(cf[1][nt], ah1, bh, cf[1][nt]);
            wmma::mma_sync(cf[1][nt], ah1, bl, cf[1][nt]);
            wmma::mma_sync(cf[1][nt], al1, bh, cf[1][nt]);
        }
    }
}

// ---------------- init / bucketing ----------------
__global__ void init_kernel(){
    int i = blockIdx.x * 256 + threadIdx.x;
    if (i < Nn*128) g_agg[i] = 0.f;
    if (i < Nn*Rr){ g_denom[i] = 0.f; g_segmax[i] = 0u; }
    if (i < Tt) g_cnt[i] = 0;
}
__global__ void hist_kernel(const int* __restrict__ nt){
    int n = blockIdx.x * 256 + threadIdx.x;
    if (n < Nn) atomicAdd(&g_cnt[nt[n]], 1);
}
__global__ void prefix_kernel(){
    if (threadIdx.x == 0){
        int s = 0;
        for (int t = 0; t < Tt; t++){
            g_off[t] = s; g_cursor[t] = s; s += g_cnt[t];
        }
        g_off[Tt] = s;
    }
}
__global__ void scatter_kernel(const int* __restrict__ nt){
    int n = blockIdx.x * 256 + threadIdx.x;
    if (n < Nn){
        int p = atomicAdd(&g_cursor[nt[n]], 1);
        g_bucket[p] = n;
    }
}
__global__ void zeropad_kernel(float* __restrict__ k, float* __restrict__ v){
    int i = blockIdx.x * 256 + threadIdx.x;
    if (i < (NP - Nn)*128){
        k[(size_t)Nn*128 + i] = 0.f;
        v[(size_t)Nn*128 + i] = 0.f;
    }
}

// ---------------- gathered writeback via smem staging (Bh region, 64 rows, ld BH_LD) ----------------
__device__ __forceinline__ void writeback_gather(float* sm, float* __restrict__ C,
                                                 const int* rows_s, int mc,
                                                 FragC cf[2][4], int wr, int wc,
                                                 int tid, float gate){
    float* stg = sm + OFF_BH;
    for (int ph = 0; ph < 2; ph++){
        __syncthreads();
        if ((wr >> 1) == ph){
            int lr0 = (wr & 1) * 32;
            #pragma unroll
            for (int f = 0; f < 2; f++)
                #pragma unroll
                for (int nt = 0; nt < 4; nt++)
                    wmma::store_matrix_sync(stg + (lr0 + f*16)*BH_LD + wc*64 + nt*16,
                                            cf[f][nt], BH_LD, wmma::mem_row_major);
        }
        __syncthreads();
        #pragma unroll
        for (int i = 0; i < 8; i++){
            int idx = tid + i*256;       // 0..2047
            int m = idx >> 5, c4 = idx & 31;
            int gm = ph*64 + m;
            if (gm < mc){
                float4 v = *reinterpret_cast<const float4*>(stg + m*BH_LD + c4*4);
                v.x *= gate; v.y *= gate; v.z *= gate; v.w *= gate;
                *reinterpret_cast<float4*>(C + (size_t)rows_s[gm]*128 + c4*4) = v;
            }
        }
    }
}

// ---------------- K1: per-type fused k/q/v projection ----------------
__global__ void __launch_bounds__(256, 1) proj_kqv_kernel(
    const float* __restrict__ h,
    const float* __restrict__ kw, const float* __restrict__ qw, const float* __restrict__ vw,
    float* __restrict__ ok, float* __restrict__ oq, float* __restrict__ ov)
{
    extern __shared__ float sm[];
    __shared__ int rows_s[128];

    int tid = threadIdx.x, wid = tid >> 5;
    int wr = wid >> 1, wc = wid & 1;
    int t = blockIdx.y;
    int base = g_off[t];
    int cnt = g_off[t+1] - base;
    int tb = blockIdx.x * 128;
    if (tb >= cnt) return;
    int mc = min(128, cnt - tb);

    if (tid < 128) rows_s[tid] = (tid < mc) ? g_bucket[base + tb + tid] : 0;

    const float* Wsrc[3] = { kw + t*16384, qw + t*16384, vw + t*16384 };
    float* Cd[3] = { ok, oq, ov };

    for (int w = 0; w < 3; w++){
        FragC cf[2][4];
        #pragma unroll
        for (int f = 0; f < 2; f++)
            #pragma unroll
            for (int nt = 0; nt < 4; nt++) wmma::fill_fragment(cf[f][nt], 0.f);

        for (int ch = 0; ch < 2; ch++){
            __syncthreads();
            stage_A_gather(sm, h, rows_s, mc, ch, tid);
            stage_B_split(sm, Wsrc[w], ch, tid);
            __syncthreads();
            mma_chunk(sm, cf, wr, wc);
        }
        writeback_gather(sm, Cd[w], rows_s, mc, cf, wr, wc, tid, 1.0f);
        __syncthreads();
    }
}

// ---------------- K2: per-relation dense GEMM, direct gmem store ----------------
__global__ void __launch_bounds__(256, 1) relproj_kernel(
    const float* __restrict__ Xk, const float* __restrict__ Xv,
    const float* __restrict__ att, const float* __restrict__ msg,
    float* __restrict__ CkA, float* __restrict__ CvM)
{
    extern __shared__ float sm[];
    int tid = threadIdx.x, wid = tid >> 5;
    int wr = wid >> 1, wc = wid & 1;
    int tile = blockIdx.x, r = blockIdx.y, z = blockIdx.z;
    const float* X = z ? Xv : Xk;
    const float* W = (z ? msg : att) + (size_t)r*16384;
    float* C = (z ? CvM : CkA) + (size_t)r*NP*128;
    int row0 = tile * 128;

    FragC cf[2][4];
    #pragma unroll
    for (int f = 0; f < 2; f++)
        #pragma unroll
        for (int nt = 0; nt < 4; nt++) wmma::fill_fragment(cf[f][nt], 0.f);

    for (int ch = 0; ch < 2; ch++){
        __syncthreads();
        stage_A_linear(sm, X, row0, ch, tid);
        stage_B_split(sm, W, ch, tid);
        __syncthreads();
        mma_chunk(sm, cf, wr, wc);
    }

    float* Crow = C + (size_t)(row0 + wr*32)*128 + wc*64;
    #pragma unroll
    for (int f = 0; f < 2; f++)
        #pragma unroll
        for (int nt = 0; nt < 4; nt++)
            wmma::store_matrix_sync(Crow + (size_t)f*16*128 + nt*16, cf[f][nt], 128, wmma::mem_row_major);
}

// ---------------- K3: per-edge score + segment max ----------------
__global__ void __launch_bounds__(256) score_kernel(
    const float* __restrict__ kA, const float* __restrict__ q,
    const int* __restrict__ src, const int* __restrict__ dst, const int* __restrict__ et,
    const float* __restrict__ pri, float* __restrict__ score, unsigned* __restrict__ segmax)
{
    int e = (blockIdx.x * blockDim.x + threadIdx.x) >> 5;
    if (e >= Ee) return;
    int lane = threadIdx.x & 31;
    int s = src[e], d = dst[e], r = et[e];
    const float4* ka = reinterpret_cast<const float4*>(kA + ((size_t)r*NP + s)*128);
    const float4* qq = reinterpret_cast<const float4*>(q + (size_t)d*128);
    float4 x = ka[lane], y = qq[lane];
    float acc = x.x*y.x + x.y*y.y + x.z*y.z + x.w*y.w;
    #pragma unroll
    for (int o = 16; o; o >>= 1) acc += __shfl_xor_sync(0xffffffffu, acc, o);
    if (lane == 0){
        float sc = acc * pri[r] * 0.08838834764831845f;
        score[e] = sc;
        atomicMax(&segmax[d*Rr + r], ford(sc));
    }
}

// ---------------- K4: exp + denom ----------------
__global__ void __launch_bounds__(256) exp_kernel(
    const float* __restrict__ score, const int* __restrict__ dst, const int* __restrict__ et,
    const unsigned* __restrict__ segmax, float* __restrict__ denom, float* __restrict__ ex)
{
    int e = blockIdx.x * 256 + threadIdx.x;
    if (e >= Ee) return;
    int seg = dst[e]*Rr + et[e];
    float m = ordf(segmax[seg]);
    float v = __expf(score[e] - m);
    ex[e] = v;
    atomicAdd(&denom[seg], v);
}

// ---------------- K5: weighted aggregation ----------------
__global__ void __launch_bounds__(256) agg_kernel(
    const float* __restrict__ vM, const float* __restrict__ ex, const float* __restrict__ denom,
    const int* __restrict__ src, const int* __restrict__ dst, const int* __restrict__ et,
    float* __restrict__ agg)
{
    int e = (blockIdx.x * blockDim.x + threadIdx.x) >> 5;
    if (e >= Ee) return;
    int lane = threadIdx.x & 31;
    int s = src[e], d = dst[e], r = et[e];
    float alpha = ex[e] / denom[d*Rr + r];
    const float4* vm = reinterpret_cast<const float4*>(vM + ((size_t)r*NP + s)*128);
    float4 v = vm[lane];
    float* out = agg + (size_t)d*128 + lane*4;
    asm volatile("red.global.add.v4.f32 [%0], {%1, %2, %3, %4};"
                 :: "l"(out), "f"(alpha*v.x), "f"(alpha*v.y), "f"(alpha*v.z), "f"(alpha*v.w)
                 : "memory");
}

// ---------------- K6: per-type output transform ----------------
__global__ void __launch_bounds__(256, 1) out_kernel(
    const float* __restrict__ agg, const float* __restrict__ aw,
    const float* __restrict__ skip, float* __restrict__ out)
{
    extern __shared__ float sm[];
    __shared__ int rows_s[128];

    int tid = threadIdx.x, wid = tid >> 5;
    int wr = wid >> 1, wc = wid & 1;
    int t = blockIdx.y;
    int base = g_off[t];
    int cnt = g_off[t+1] - base;
    int tb = blockIdx.x * 128;
    if (tb >= cnt) return;
    int mc = min(128, cnt - tb);

    if (tid < 128) rows_s[tid] = (tid < mc) ? g_bucket[base + tb + tid] : 0;

    FragC cf[2][4];
    #pragma unroll
    for (int f = 0; f < 2; f++)
        #pragma unroll
        for (int nt = 0; nt < 4; nt++) wmma::fill_fragment(cf[f][nt], 0.f);

    const float* W = aw + (size_t)t*16384;
    for (int ch = 0; ch < 2; ch++){
        __syncthreads();
        stage_A_gather(sm, agg, rows_s, mc, ch, tid);
        stage_B_split(sm, W, ch, tid);
        __syncthreads();
        mma_chunk(sm, cf, wr, wc);
    }

    float gate = 1.f / (1.f + __expf(-skip[t]));
    writeback_gather(sm, out, rows_s, mc, cf, wr, wc, tid, gate);
}

// ---------------- launch ----------------
extern "C" void kernel_launch(void* const* d_in, const int* in_sizes, int n_in,
                              void* d_out, int out_size)
{
    const float* h     = (const float*)d_in[0];
    const int*   adj   = (const int*)d_in[1];
    const int*   etype = (const int*)d_in[2];
    const int*   ntype = (const int*)d_in[3];
    const float* kw    = (const float*)d_in[6];
    const float* qw    = (const float*)d_in[7];
    const float* vw    = (const float*)d_in[8];
    const float* aw    = (const float*)d_in[9];
    const float* pri   = (const float*)d_in[10];
    const float* att   = (const float*)d_in[11];
    const float* msg   = (const float*)d_in[12];
    const float* skip  = (const float*)d_in[13];
    const int* src = adj;
    const int* dst = adj + Ee;
    float* out = (float*)d_out;

    cudaFuncSetAttribute(proj_kqv_kernel, cudaFuncAttributeMaxDynamicSharedMemorySize, GEMM_SMEM);
    cudaFuncSetAttribute(relproj_kernel,  cudaFuncAttributeMaxDynamicSharedMemorySize, GEMM_SMEM);
    cudaFuncSetAttribute(out_kernel,      cudaFuncAttributeMaxDynamicSharedMemorySize, GEMM_SMEM);

    void *pk, *pq, *pv, *pkA, *pvM, *pscore, *pex, *psegmax, *pdenom, *pagg;
    cudaGetSymbolAddress(&pk, g_k);
    cudaGetSymbolAddress(&pq, g_q);
    cudaGetSymbolAddress(&pv, g_v);
    cudaGetSymbolAddress(&pkA, g_kA);
    cudaGetSymbolAddress(&pvM, g_vM);
    cudaGetSymbolAddress(&pscore, g_score);
    cudaGetSymbolAddress(&pex, g_ex);
    cudaGetSymbolAddress(&psegmax, g_segmax);
    cudaGetSymbolAddress(&pdenom, g_denom);
    cudaGetSymbolAddress(&pagg, g_agg);

    init_kernel<<<(Nn*128 + 255)/256, 256>>>();
    hist_kernel<<<(Nn + 255)/256, 256>>>(ntype);
    prefix_kernel<<<1, 32>>>();
    scatter_kernel<<<(Nn + 255)/256, 256>>>(ntype);
    zeropad_kernel<<<((NP - Nn)*128 + 255)/256, 256>>>((float*)pk, (float*)pv);

    dim3 gT((Nn + 127)/128, Tt);
    proj_kqv_kernel<<<gT, 256, GEMM_SMEM>>>(h, kw, qw, vw,
                                            (float*)pk, (float*)pq, (float*)pv);

    dim3 gR(NT, Rr, 2);
    relproj_kernel<<<gR, 256, GEMM_SMEM>>>((const float*)pk, (const float*)pv,
                                           att, msg, (float*)pkA, (float*)pvM);

    int score_blocks = (Ee + 7) / 8;
    score_kernel<<<score_blocks, 256>>>((const float*)pkA, (const float*)pq,
                                        src, dst, etype, pri,
                                        (float*)pscore, (unsigned*)psegmax);

    exp_kernel<<<(Ee + 255)/256, 256>>>((const float*)pscore, dst, etype,
                                        (const unsigned*)psegmax,
                                        (float*)pdenom, (float*)pex);

    agg_kernel<<<score_blocks, 256>>>((const float*)pvM, (const float*)pex,
                                      (const float*)pdenom, src, dst, etype,
                                      (float*)pagg);

    out_kernel<<<gT, 256, GEMM_SMEM>>>((const float*)pagg, aw, skip, out);
}

// round 5
// speedup vs baseline: 1.0605x; 1.0605x over previous
#include <cuda_runtime.h>
#include <mma.h>
#include <math.h>
#include <cstdint>

using namespace nvcuda;

#define Nn 50000
#define Ee 500000
#define Tt 8
#define Rr 8
#define NT 391                 // ceil(50000/128) row tiles
#define NP (NT*128)            // padded rows = 50048

// smem (floats): As[128][68] raw A K-chunk, Bh[64][132], Bl[64][132]
#define AS_LD 68
#define B_LD 132
#define SM_AS (128*AS_LD)          // 8704
#define SM_B  (64*B_LD)            // 8448
#define OFF_AS 0
#define OFF_BH (SM_AS)
#define OFF_BL (SM_AS + SM_B)
#define GEMM_SMEM ((SM_AS + 2*SM_B)*4)   // 102400 B -> 2 blocks/SM

// ---------------- device scratch ----------------
__device__ float g_k[(size_t)NP*128];
__device__ float g_q[(size_t)Nn*128];
__device__ float g_v[(size_t)NP*128];
__device__ float g_kA[(size_t)Rr*NP*128];
__device__ float g_vM[(size_t)Rr*NP*128];
__device__ float g_score[Ee];
__device__ float g_ex[Ee];
__device__ unsigned g_segmax[Nn*Rr];
__device__ float g_denom[Nn*Rr];
__device__ float g_agg[(size_t)Nn*128];
__device__ int g_bucket[Nn];
__device__ int g_cnt[Tt];
__device__ int g_off[Tt+1];
__device__ int g_cursor[Tt];

// ---------------- helpers ----------------
__device__ __forceinline__ float to_tf32(float x){
    float r;
    asm("cvt.rna.tf32.f32 %0, %1;" : "=f"(r) : "f"(x));
    return r;
}
__device__ __forceinline__ unsigned ford(float f){
    unsigned u = __float_as_uint(f);
    return (u & 0x80000000u) ? ~u : (u | 0x80000000u);
}
__device__ __forceinline__ float ordf(unsigned u){
    return (u & 0x80000000u) ? __uint_as_float(u & 0x7fffffffu) : __uint_as_float(~u);
}

typedef wmma::fragment<wmma::matrix_a, 16, 16, 8, wmma::precision::tf32, wmma::row_major> FragA;
typedef wmma::fragment<wmma::matrix_b, 16, 16, 8, wmma::precision::tf32, wmma::row_major> FragB;
typedef wmma::fragment<wmma::accumulator, 16, 16, 8, float> FragC;

__device__ __forceinline__ void split4(float4 v, float4& hi, float4& lo){
    hi.x = to_tf32(v.x); lo.x = to_tf32(v.x - hi.x);
    hi.y = to_tf32(v.y); lo.y = to_tf32(v.y - hi.y);
    hi.z = to_tf32(v.z); lo.z = to_tf32(v.z - hi.z);
    hi.w = to_tf32(v.w); lo.w = to_tf32(v.w - hi.w);
}
__device__ __forceinline__ void split_a(const FragA& raw, FragA& hi, FragA& lo){
    #pragma unroll
    for (int i = 0; i < raw.num_elements; i++){
        float x = raw.x[i];
        float h = to_tf32(x);
        hi.x[i] = h;
        lo.x[i] = to_tf32(x - h);
    }
}

// stage 128-row x 64-col A chunk (gathered rows), raw fp32
__device__ __forceinline__ void stage_A_gather(float* sm, const float* __restrict__ X,
                                               const int* rows_s, int mc, int ch, int tid){
    #pragma unroll
    for (int i = 0; i < 8; i++){
        int idx = tid + i*256;           // 0..2047
        int m = idx >> 4, c4 = idx & 15; // 128 rows x 16 float4
        float4 v = make_float4(0.f,0.f,0.f,0.f);
        if (m < mc) v = *reinterpret_cast<const float4*>(X + (size_t)rows_s[m]*128 + ch*64 + c4*4);
        *reinterpret_cast<float4*>(sm + OFF_AS + m*AS_LD + c4*4) = v;
    }
}
__device__ __forceinline__ void stage_A_linear(float* sm, const float* __restrict__ X,
                                               int row0, int ch, int tid){
    #pragma unroll
    for (int i = 0; i < 8; i++){
        int idx = tid + i*256;
        int m = idx >> 4, c4 = idx & 15;
        float4 v = *reinterpret_cast<const float4*>(X + (size_t)(row0 + m)*128 + ch*64 + c4*4);
        *reinterpret_cast<float4*>(sm + OFF_AS + m*AS_LD + c4*4) = v;
    }
}
// stage 64-row x 128-col B chunk, pre-split into Bh/Bl planes
__device__ __forceinline__ void stage_B_split(float* sm, const float* __restrict__ W,
                                              int ch, int tid){
    #pragma unroll
    for (int i = 0; i < 8; i++){
        int idx = tid + i*256;           // 0..2047
        int row = idx >> 5, c4 = idx & 31;
        float4 v = *reinterpret_cast<const float4*>(W + (size_t)(ch*64 + row)*128 + c4*4);
        float4 hi, lo; split4(v, hi, lo);
        *reinterpret_cast<float4*>(sm + OFF_BH + row*B_LD + c4*4) = hi;
        *reinterpret_cast<float4*>(sm + OFF_BL + row*B_LD + c4*4) = lo;
    }
}

// 3xTF32 MMA over one 64-wide K chunk. Warp: rows wid*16..+16, all 128 cols (8 nt).
__device__ __forceinline__ void mma_chunk(const float* sm, FragC cf[8], int wrow0){
    #pragma unroll
    for (int kk = 0; kk < 64; kk += 8){
        FragA ar, ah, al;
        wmma::load_matrix_sync(ar, sm + OFF_AS + wrow0*AS_LD + kk, AS_LD);
        split_a(ar, ah, al);
        #pragma unroll
        for (int nt = 0; nt < 8; nt++){
            FragB bh, bl;
            wmma::load_matrix_sync(bh, sm + OFF_BH + kk*B_LD + nt*16, B_LD);
            wmma::load_matrix_sync(bl, sm + OFF_BL + kk*B_LD + nt*16, B_LD);
            wmma::mma_sync(cf[nt], ah, bl, cf[nt]);
            wmma::mma_sync(cf[nt], al, bh, cf[nt]);
            wmma::mma_sync(cf[nt], ah, bh, cf[nt]);
        }
    }
}

// ---------------- init / bucketing ----------------
__global__ void init_kernel(){
    int i = blockIdx.x * 256 + threadIdx.x;
    if (i < Nn*128) g_agg[i] = 0.f;
    if (i < Nn*Rr){ g_denom[i] = 0.f; g_segmax[i] = 0u; }
    if (i < Tt) g_cnt[i] = 0;
}
__global__ void hist_kernel(const int* __restrict__ nt){
    int n = blockIdx.x * 256 + threadIdx.x;
    if (n < Nn) atomicAdd(&g_cnt[nt[n]], 1);
}
__global__ void prefix_kernel(){
    if (threadIdx.x == 0){
        int s = 0;
        for (int t = 0; t < Tt; t++){
            g_off[t] = s; g_cursor[t] = s; s += g_cnt[t];
        }
        g_off[Tt] = s;
    }
}
__global__ void scatter_kernel(const int* __restrict__ nt){
    int n = blockIdx.x * 256 + threadIdx.x;
    if (n < Nn){
        int p = atomicAdd(&g_cursor[nt[n]], 1);
        g_bucket[p] = n;
    }
}
__global__ void zeropad_kernel(float* __restrict__ k, float* __restrict__ v){
    int i = blockIdx.x * 256 + threadIdx.x;
    if (i < (NP - Nn)*128){
        k[(size_t)Nn*128 + i] = 0.f;
        v[(size_t)Nn*128 + i] = 0.f;
    }
}

// ---------------- gathered writeback via smem staging (Bh plane, 64 rows) ----------------
__device__ __forceinline__ void writeback_gather(float* sm, float* __restrict__ C,
                                                 const int* rows_s, int mc,
                                                 FragC cf[8], int wid, int tid, float gate){
    float* stg = sm + OFF_BH;
    for (int ph = 0; ph < 2; ph++){
        __syncthreads();
        if ((wid >> 2) == ph){
            int lr0 = (wid & 3) * 16;
            #pragma unroll
            for (int nt = 0; nt < 8; nt++)
                wmma::store_matrix_sync(stg + lr0*B_LD + nt*16, cf[nt], B_LD, wmma::mem_row_major);
        }
        __syncthreads();
        #pragma unroll
        for (int i = 0; i < 8; i++){
            int idx = tid + i*256;       // 0..2047
            int m = idx >> 5, c4 = idx & 31;
            int gm = ph*64 + m;
            if (gm < mc){
                float4 v = *reinterpret_cast<const float4*>(stg + m*B_LD + c4*4);
                v.x *= gate; v.y *= gate; v.z *= gate; v.w *= gate;
                *reinterpret_cast<float4*>(C + (size_t)rows_s[gm]*128 + c4*4) = v;
            }
        }
    }
}

// ---------------- K1: per-type fused k/q/v projection ----------------
__global__ void __launch_bounds__(256, 2) proj_kqv_kernel(
    const float* __restrict__ h,
    const float* __restrict__ kw, const float* __restrict__ qw, const float* __restrict__ vw,
    float* __restrict__ ok, float* __restrict__ oq, float* __restrict__ ov)
{
    extern __shared__ float sm[];
    __shared__ int rows_s[128];

    int tid = threadIdx.x, wid = tid >> 5;
    int t = blockIdx.y;
    int base = g_off[t];
    int cnt = g_off[t+1] - base;
    int tb = blockIdx.x * 128;
    if (tb >= cnt) return;
    int mc = min(128, cnt - tb);

    if (tid < 128) rows_s[tid] = (tid < mc) ? g_bucket[base + tb + tid] : 0;
    __syncthreads();

    const float* Wsrc[3] = { kw + t*16384, qw + t*16384, vw + t*16384 };
    float* Cd[3] = { ok, oq, ov };
    int wrow0 = wid * 16;

    for (int w = 0; w < 3; w++){
        FragC cf[8];
        #pragma unroll
        for (int nt = 0; nt < 8; nt++) wmma::fill_fragment(cf[nt], 0.f);

        for (int ch = 0; ch < 2; ch++){
            __syncthreads();
            stage_A_gather(sm, h, rows_s, mc, ch, tid);
            stage_B_split(sm, Wsrc[w], ch, tid);
            __syncthreads();
            mma_chunk(sm, cf, wrow0);
        }
        writeback_gather(sm, Cd[w], rows_s, mc, cf, wid, tid, 1.0f);
        __syncthreads();
    }
}

// ---------------- K2: per-relation dense GEMM, direct gmem store ----------------
__global__ void __launch_bounds__(256, 2) relproj_kernel(
    const float* __restrict__ Xk, const float* __restrict__ Xv,
    const float* __restrict__ att, const float* __restrict__ msg,
    float* __restrict__ CkA, float* __restrict__ CvM)
{
    extern __shared__ float sm[];
    int tid = threadIdx.x, wid = tid >> 5;
    int tile = blockIdx.x, r = blockIdx.y, z = blockIdx.z;
    const float* X = z ? Xv : Xk;
    const float* W = (z ? msg : att) + (size_t)r*16384;
    float* C = (z ? CvM : CkA) + (size_t)r*NP*128;
    int row0 = tile * 128;
    int wrow0 = wid * 16;

    FragC cf[8];
    #pragma unroll
    for (int nt = 0; nt < 8; nt++) wmma::fill_fragment(cf[nt], 0.f);

    for (int ch = 0; ch < 2; ch++){
        __syncthreads();
        stage_A_linear(sm, X, row0, ch, tid);
        stage_B_split(sm, W, ch, tid);
        __syncthreads();
        mma_chunk(sm, cf, wrow0);
    }

    float* Crow = C + (size_t)(row0 + wrow0)*128;
    #pragma unroll
    for (int nt = 0; nt < 8; nt++)
        wmma::store_matrix_sync(Crow + nt*16, cf[nt], 128, wmma::mem_row_major);
}

// ---------------- K3: per-edge score + segment max ----------------
__global__ void __launch_bounds__(256) score_kernel(
    const float* __restrict__ kA, const float* __restrict__ q,
    const int* __restrict__ src, const int* __restrict__ dst, const int* __restrict__ et,
    const float* __restrict__ pri, float* __restrict__ score, unsigned* __restrict__ segmax)
{
    int e = (blockIdx.x * blockDim.x + threadIdx.x) >> 5;
    if (e >= Ee) return;
    int lane = threadIdx.x & 31;
    int s = src[e], d = dst[e], r = et[e];
    const float4* ka = reinterpret_cast<const float4*>(kA + ((size_t)r*NP + s)*128);
    const float4* qq = reinterpret_cast<const float4*>(q + (size_t)d*128);
    float4 x = ka[lane], y = qq[lane];
    float acc = x.x*y.x + x.y*y.y + x.z*y.z + x.w*y.w;
    #pragma unroll
    for (int o = 16; o; o >>= 1) acc += __shfl_xor_sync(0xffffffffu, acc, o);
    if (lane == 0){
        float sc = acc * pri[r] * 0.08838834764831845f;
        score[e] = sc;
        atomicMax(&segmax[d*Rr + r], ford(sc));
    }
}

// ---------------- K4: exp + denom ----------------
__global__ void __launch_bounds__(256) exp_kernel(
    const float* __restrict__ score, const int* __restrict__ dst, const int* __restrict__ et,
    const unsigned* __restrict__ segmax, float* __restrict__ denom, float* __restrict__ ex)
{
    int e = blockIdx.x * 256 + threadIdx.x;
    if (e >= Ee) return;
    int seg = dst[e]*Rr + et[e];
    float m = ordf(segmax[seg]);
    float v = __expf(score[e] - m);
    ex[e] = v;
    atomicAdd(&denom[seg], v);
}

// ---------------- K5: weighted aggregation ----------------
__global__ void __launch_bounds__(256) agg_kernel(
    const float* __restrict__ vM, const float* __restrict__ ex, const float* __restrict__ denom,
    const int* __restrict__ src, const int* __restrict__ dst, const int* __restrict__ et,
    float* __restrict__ agg)
{
    int e = (blockIdx.x * blockDim.x + threadIdx.x) >> 5;
    if (e >= Ee) return;
    int lane = threadIdx.x & 31;
    int s = src[e], d = dst[e], r = et[e];
    float alpha = ex[e] / denom[d*Rr + r];
    const float4* vm = reinterpret_cast<const float4*>(vM + ((size_t)r*NP + s)*128);
    float4 v = vm[lane];
    float* out = agg + (size_t)d*128 + lane*4;
    asm volatile("red.global.add.v4.f32 [%0], {%1, %2, %3, %4};"
                 :: "l"(out), "f"(alpha*v.x), "f"(alpha*v.y), "f"(alpha*v.z), "f"(alpha*v.w)
                 : "memory");
}

// ---------------- K6: per-type output transform ----------------
__global__ void __launch_bounds__(256, 2) out_kernel(
    const float* __restrict__ agg, const float* __restrict__ aw,
    const float* __restrict__ skip, float* __restrict__ out)
{
    extern __shared__ float sm[];
    __shared__ int rows_s[128];

    int tid = threadIdx.x, wid = tid >> 5;
    int t = blockIdx.y;
    int base = g_off[t];
    int cnt = g_off[t+1] - base;
    int tb = blockIdx.x * 128;
    if (tb >= cnt) return;
    int mc = min(128, cnt - tb);

    if (tid < 128) rows_s[tid] = (tid < mc) ? g_bucket[base + tb + tid] : 0;
    __syncthreads();

    FragC cf[8];
    #pragma unroll
    for (int nt = 0; nt < 8; nt++) wmma::fill_fragment(cf[nt], 0.f);

    int wrow0 = wid * 16;
    const float* W = aw + (size_t)t*16384;
    for (int ch = 0; ch < 2; ch++){
        __syncthreads();
        stage_A_gather(sm, agg, rows_s, mc, ch, tid);
        stage_B_split(sm, W, ch, tid);
        __syncthreads();
        mma_chunk(sm, cf, wrow0);
    }

    float gate = 1.f / (1.f + __expf(-skip[t]));
    writeback_gather(sm, out, rows_s, mc, cf, wid, tid, gate);
}

// ---------------- launch ----------------
extern "C" void kernel_launch(void* const* d_in, const int* in_sizes, int n_in,
                              void* d_out, int out_size)
{
    const float* h     = (const float*)d_in[0];
    const int*   adj   = (const int*)d_in[1];
    const int*   etype = (const int*)d_in[2];
    const int*   ntype = (const int*)d_in[3];
    const float* kw    = (const float*)d_in[6];
    const float* qw    = (const float*)d_in[7];
    const float* vw    = (const float*)d_in[8];
    const float* aw    = (const float*)d_in[9];
    const float* pri   = (const float*)d_in[10];
    const float* att   = (const float*)d_in[11];
    const float* msg   = (const float*)d_in[12];
    const float* skip  = (const float*)d_in[13];
    const int* src = adj;
    const int* dst = adj + Ee;
    float* out = (float*)d_out;

    cudaFuncSetAttribute(proj_kqv_kernel, cudaFuncAttributeMaxDynamicSharedMemorySize, GEMM_SMEM);
    cudaFuncSetAttribute(relproj_kernel,  cudaFuncAttributeMaxDynamicSharedMemorySize, GEMM_SMEM);
    cudaFuncSetAttribute(out_kernel,      cudaFuncAttributeMaxDynamicSharedMemorySize, GEMM_SMEM);

    void *pk, *pq, *pv, *pkA, *pvM, *pscore, *pex, *psegmax, *pdenom, *pagg;
    cudaGetSymbolAddress(&pk, g_k);
    cudaGetSymbolAddress(&pq, g_q);
    cudaGetSymbolAddress(&pv, g_v);
    cudaGetSymbolAddress(&pkA, g_kA);
    cudaGetSymbolAddress(&pvM, g_vM);
    cudaGetSymbolAddress(&pscore, g_score);
    cudaGetSymbolAddress(&pex, g_ex);
    cudaGetSymbolAddress(&psegmax, g_segmax);
    cudaGetSymbolAddress(&pdenom, g_denom);
    cudaGetSymbolAddress(&pagg, g_agg);

    init_kernel<<<(Nn*128 + 255)/256, 256>>>();
    hist_kernel<<<(Nn + 255)/256, 256>>>(ntype);
    prefix_kernel<<<1, 32>>>();
    scatter_kernel<<<(Nn + 255)/256, 256>>>(ntype);
    zeropad_kernel<<<((NP - Nn)*128 + 255)/256, 256>>>((float*)pk, (float*)pv);

    dim3 gT((Nn + 127)/128, Tt);
    proj_kqv_kernel<<<gT, 256, GEMM_SMEM>>>(h, kw, qw, vw,
                                            (float*)pk, (float*)pq, (float*)pv);

    dim3 gR(NT, Rr, 2);
    relproj_kernel<<<gR, 256, GEMM_SMEM>>>((const float*)pk, (const float*)pv,
                                           att, msg, (float*)pkA, (float*)pvM);

    int score_blocks = (Ee + 7) / 8;
    score_kernel<<<score_blocks, 256>>>((const float*)pkA, (const float*)pq,
                                        src, dst, etype, pri,
                                        (float*)pscore, (unsigned*)psegmax);

    exp_kernel<<<(Ee + 255)/256, 256>>>((const float*)pscore, dst, etype,
                                        (const unsigned*)psegmax,
                                        (float*)pdenom, (float*)pex);

    agg_kernel<<<score_blocks, 256>>>((const float*)pvM, (const float*)pex,
                                      (const float*)pdenom, src, dst, etype,
                                      (float*)pagg);

    out_kernel<<<gT, 256, GEMM_SMEM>>>((const float*)pagg, aw, skip, out);
}

// round 6
// speedup vs baseline: 2.5431x; 2.3979x over previous
#include <cuda_runtime.h>
#include <mma.h>
#include <cuda_fp16.h>
#include <math.h>
#include <cstdint>

using namespace nvcuda;

#define Nn 50000
#define Ee 500000
#define Tt 8
#define Rr 8
#define NT 391                 // ceil(50000/128) row tiles
#define NP (NT*128)            // padded rows = 50048

// smem (bytes): Ah[128][136]h, Al[128][136]h, Bh[64][136]h, Bl[64][136]h
#define LDA 136
#define LDB 136
#define OFF_AH 0
#define OFF_AL 34816           // 128*136*2
#define OFF_BH 69632
#define OFF_BL 87040           // +64*136*2
#define GEMM_SMEM 104448       // 2 blocks/SM (<=116736)
#define STG_LD 132             // fp32 writeback staging ld (in B region)

// ---------------- device scratch ----------------
__device__ float g_k[(size_t)NP*128];
__device__ float g_q[(size_t)Nn*128];
__device__ float g_v[(size_t)NP*128];
__device__ float g_kA[(size_t)Rr*NP*128];
__device__ float g_vM[(size_t)Rr*NP*128];
__device__ float g_score[Ee];
__device__ float g_ex[Ee];
__device__ unsigned g_segmax[Nn*Rr];
__device__ float g_denom[Nn*Rr];
__device__ float g_agg[(size_t)Nn*128];
__device__ int g_bucket[Nn];
__device__ int g_cnt[Tt];
__device__ int g_off[Tt+1];
__device__ int g_cursor[Tt];

// ---------------- helpers ----------------
__device__ __forceinline__ unsigned ford(float f){
    unsigned u = __float_as_uint(f);
    return (u & 0x80000000u) ? ~u : (u | 0x80000000u);
}
__device__ __forceinline__ float ordf(unsigned u){
    return (u & 0x80000000u) ? __uint_as_float(u & 0x7fffffffu) : __uint_as_float(~u);
}

typedef wmma::fragment<wmma::matrix_a, 16, 16, 16, __half, wmma::row_major> FragA;
typedef wmma::fragment<wmma::matrix_b, 16, 16, 16, __half, wmma::row_major> FragB;
typedef wmma::fragment<wmma::accumulator, 16, 16, 16, float> FragC;

__device__ __forceinline__ void split2h(float x, __half& a, __half& b){
    a = __float2half_rn(x);
    b = __float2half_rn(x - __half2float(a));
}
// split a float4 into hi/lo fp16 quads and store (8B each plane)
__device__ __forceinline__ void split_store4(float4 v, __half* d1, __half* d2){
    __half a0,b0,a1,b1,a2,b2,a3,b3;
    split2h(v.x,a0,b0); split2h(v.y,a1,b1); split2h(v.z,a2,b2); split2h(v.w,a3,b3);
    __half2* p1 = reinterpret_cast<__half2*>(d1);
    p1[0] = __halves2half2(a0,a1);
    p1[1] = __halves2half2(a2,a3);
    __half2* p2 = reinterpret_cast<__half2*>(d2);
    p2[0] = __halves2half2(b0,b1);
    p2[1] = __halves2half2(b2,b3);
}

// stage full-width A (128 rows x 128 cols), gathered rows, split into Ah/Al
__device__ __forceinline__ void stage_A_gather(char* smem, const float* __restrict__ X,
                                               const int* rows_s, int mc, int tid){
    __half* Ah = reinterpret_cast<__half*>(smem + OFF_AH);
    __half* Al = reinterpret_cast<__half*>(smem + OFF_AL);
    #pragma unroll
    for (int i = 0; i < 16; i++){
        int idx = tid + i*256;           // 0..4095
        int m = idx >> 5, c4 = idx & 31;
        float4 v = make_float4(0.f,0.f,0.f,0.f);
        if (m < mc) v = *reinterpret_cast<const float4*>(X + (size_t)rows_s[m]*128 + c4*4);
        split_store4(v, Ah + m*LDA + c4*4, Al + m*LDA + c4*4);
    }
}
__device__ __forceinline__ void stage_A_linear(char* smem, const float* __restrict__ X,
                                               int row0, int tid){
    __half* Ah = reinterpret_cast<__half*>(smem + OFF_AH);
    __half* Al = reinterpret_cast<__half*>(smem + OFF_AL);
    #pragma unroll
    for (int i = 0; i < 16; i++){
        int idx = tid + i*256;
        int m = idx >> 5, c4 = idx & 31;
        float4 v = *reinterpret_cast<const float4*>(X + (size_t)(row0 + m)*128 + c4*4);
        split_store4(v, Ah + m*LDA + c4*4, Al + m*LDA + c4*4);
    }
}
// stage B K-chunk (64 K-rows x 128 cols), split into Bh/Bl
__device__ __forceinline__ void stage_B_split(char* smem, const float* __restrict__ W,
                                              int ch, int tid){
    __half* Bh = reinterpret_cast<__half*>(smem + OFF_BH);
    __half* Bl = reinterpret_cast<__half*>(smem + OFF_BL);
    #pragma unroll
    for (int i = 0; i < 8; i++){
        int idx = tid + i*256;           // 0..2047
        int row = idx >> 5, c4 = idx & 31;
        float4 v = *reinterpret_cast<const float4*>(W + (size_t)(ch*64 + row)*128 + c4*4);
        split_store4(v, Bh + row*LDB + c4*4, Bl + row*LDB + c4*4);
    }
}

// 3-term fp16 MMA over one 64-wide K chunk. Warp: rows wrow0..+16, all 128 cols.
__device__ __forceinline__ void mma_chunk(const char* smem, FragC cf[8], int wrow0, int ch){
    const __half* Ah = reinterpret_cast<const __half*>(smem + OFF_AH);
    const __half* Al = reinterpret_cast<const __half*>(smem + OFF_AL);
    const __half* Bh = reinterpret_cast<const __half*>(smem + OFF_BH);
    const __half* Bl = reinterpret_cast<const __half*>(smem + OFF_BL);
    #pragma unroll
    for (int kk2 = 0; kk2 < 64; kk2 += 16){
        int kk = ch*64 + kk2;
        FragA ah, al;
        wmma::load_matrix_sync(ah, Ah + wrow0*LDA + kk, LDA);
        wmma::load_matrix_sync(al, Al + wrow0*LDA + kk, LDA);
        #pragma unroll
        for (int nt = 0; nt < 8; nt++){
            FragB bh, bl;
            wmma::load_matrix_sync(bh, Bh + kk2*LDB + nt*16, LDB);
            wmma::load_matrix_sync(bl, Bl + kk2*LDB + nt*16, LDB);
            wmma::mma_sync(cf[nt], ah, bl, cf[nt]);
            wmma::mma_sync(cf[nt], al, bh, cf[nt]);
            wmma::mma_sync(cf[nt], ah, bh, cf[nt]);
        }
    }
}

// ---------------- init / bucketing ----------------
__global__ void init_kernel(){
    int i = blockIdx.x * 256 + threadIdx.x;
    if (i < Nn*128) g_agg[i] = 0.f;
    if (i < Nn*Rr){ g_denom[i] = 0.f; g_segmax[i] = 0u; }
    if (i < Tt) g_cnt[i] = 0;
}
__global__ void hist_kernel(const int* __restrict__ nt){
    int n = blockIdx.x * 256 + threadIdx.x;
    if (n < Nn) atomicAdd(&g_cnt[nt[n]], 1);
}
__global__ void prefix_kernel(){
    if (threadIdx.x == 0){
        int s = 0;
        for (int t = 0; t < Tt; t++){
            g_off[t] = s; g_cursor[t] = s; s += g_cnt[t];
        }
        g_off[Tt] = s;
    }
}
__global__ void scatter_kernel(const int* __restrict__ nt){
    int n = blockIdx.x * 256 + threadIdx.x;
    if (n < Nn){
        int p = atomicAdd(&g_cursor[nt[n]], 1);
        g_bucket[p] = n;
    }
}
__global__ void zeropad_kernel(float* __restrict__ k, float* __restrict__ v){
    int i = blockIdx.x * 256 + threadIdx.x;
    if (i < (NP - Nn)*128){
        k[(size_t)Nn*128 + i] = 0.f;
        v[(size_t)Nn*128 + i] = 0.f;
    }
}

// ---------------- gathered writeback via fp32 staging in B region ----------------
__device__ __forceinline__ void writeback_gather(char* smem, float* __restrict__ C,
                                                 const int* rows_s, int mc,
                                                 FragC cf[8], int wid, int tid, float gate){
    float* stg = reinterpret_cast<float*>(smem + OFF_BH);
    for (int ph = 0; ph < 2; ph++){
        __syncthreads();
        if ((wid >> 2) == ph){
            int lr0 = (wid & 3) * 16;
            #pragma unroll
            for (int nt = 0; nt < 8; nt++)
                wmma::store_matrix_sync(stg + lr0*STG_LD + nt*16, cf[nt], STG_LD, wmma::mem_row_major);
        }
        __syncthreads();
        #pragma unroll
        for (int i = 0; i < 8; i++){
            int idx = tid + i*256;       // 0..2047
            int m = idx >> 5, c4 = idx & 31;
            int gm = ph*64 + m;
            if (gm < mc){
                float4 v = *reinterpret_cast<const float4*>(stg + m*STG_LD + c4*4);
                v.x *= gate; v.y *= gate; v.z *= gate; v.w *= gate;
                *reinterpret_cast<float4*>(C + (size_t)rows_s[gm]*128 + c4*4) = v;
            }
        }
    }
}

// ---------------- K1: per-type fused k/q/v projection ----------------
__global__ void __launch_bounds__(256, 2) proj_kqv_kernel(
    const float* __restrict__ h,
    const float* __restrict__ kw, const float* __restrict__ qw, const float* __restrict__ vw,
    float* __restrict__ ok, float* __restrict__ oq, float* __restrict__ ov)
{
    extern __shared__ char smem[];
    __shared__ int rows_s[128];

    int tid = threadIdx.x, wid = tid >> 5;
    int t = blockIdx.y;
    int base = g_off[t];
    int cnt = g_off[t+1] - base;
    int tb = blockIdx.x * 128;
    if (tb >= cnt) return;
    int mc = min(128, cnt - tb);

    if (tid < 128) rows_s[tid] = (tid < mc) ? g_bucket[base + tb + tid] : 0;
    __syncthreads();
    stage_A_gather(smem, h, rows_s, mc, tid);

    const float* Wsrc[3] = { kw + t*16384, qw + t*16384, vw + t*16384 };
    float* Cd[3] = { ok, oq, ov };
    int wrow0 = wid * 16;

    for (int w = 0; w < 3; w++){
        FragC cf[8];
        #pragma unroll
        for (int nt = 0; nt < 8; nt++) wmma::fill_fragment(cf[nt], 0.f);

        for (int ch = 0; ch < 2; ch++){
            __syncthreads();
            stage_B_split(smem, Wsrc[w], ch, tid);
            __syncthreads();
            mma_chunk(smem, cf, wrow0, ch);
        }
        writeback_gather(smem, Cd[w], rows_s, mc, cf, wid, tid, 1.0f);
        __syncthreads();
    }
}

// ---------------- K2: per-relation dense GEMM, direct gmem store ----------------
__global__ void __launch_bounds__(256, 2) relproj_kernel(
    const float* __restrict__ Xk, const float* __restrict__ Xv,
    const float* __restrict__ att, const float* __restrict__ msg,
    float* __restrict__ CkA, float* __restrict__ CvM)
{
    extern __shared__ char smem[];
    int tid = threadIdx.x, wid = tid >> 5;
    int tile = blockIdx.x, r = blockIdx.y, z = blockIdx.z;
    const float* X = z ? Xv : Xk;
    const float* W = (z ? msg : att) + (size_t)r*16384;
    float* C = (z ? CvM : CkA) + (size_t)r*NP*128;
    int row0 = tile * 128;
    int wrow0 = wid * 16;

    stage_A_linear(smem, X, row0, tid);

    FragC cf[8];
    #pragma unroll
    for (int nt = 0; nt < 8; nt++) wmma::fill_fragment(cf[nt], 0.f);

    for (int ch = 0; ch < 2; ch++){
        __syncthreads();
        stage_B_split(smem, W, ch, tid);
        __syncthreads();
        mma_chunk(smem, cf, wrow0, ch);
    }

    float* Crow = C + (size_t)(row0 + wrow0)*128;
    #pragma unroll
    for (int nt = 0; nt < 8; nt++)
        wmma::store_matrix_sync(Crow + nt*16, cf[nt], 128, wmma::mem_row_major);
}

// ---------------- K3: per-edge score + segment max ----------------
__global__ void __launch_bounds__(256) score_kernel(
    const float* __restrict__ kA, const float* __restrict__ q,
    const int* __restrict__ src, const int* __restrict__ dst, const int* __restrict__ et,
    const float* __restrict__ pri, float* __restrict__ score, unsigned* __restrict__ segmax)
{
    int e = (blockIdx.x * blockDim.x + threadIdx.x) >> 5;
    if (e >= Ee) return;
    int lane = threadIdx.x & 31;
    int s = src[e], d = dst[e], r = et[e];
    const float4* ka = reinterpret_cast<const float4*>(kA + ((size_t)r*NP + s)*128);
    const float4* qq = reinterpret_cast<const float4*>(q + (size_t)d*128);
    float4 x = ka[lane], y = qq[lane];
    float acc = x.x*y.x + x.y*y.y + x.z*y.z + x.w*y.w;
    #pragma unroll
    for (int o = 16; o; o >>= 1) acc += __shfl_xor_sync(0xffffffffu, acc, o);
    if (lane == 0){
        float sc = acc * pri[r] * 0.08838834764831845f;
        score[e] = sc;
        atomicMax(&segmax[d*Rr + r], ford(sc));
    }
}

// ---------------- K4: exp + denom ----------------
__global__ void __launch_bounds__(256) exp_kernel(
    const float* __restrict__ score, const int* __restrict__ dst, const int* __restrict__ et,
    const unsigned* __restrict__ segmax, float* __restrict__ denom, float* __restrict__ ex)
{
    int e = blockIdx.x * 256 + threadIdx.x;
    if (e >= Ee) return;
    int seg = dst[e]*Rr + et[e];
    float m = ordf(segmax[seg]);
    float v = __expf(score[e] - m);
    ex[e] = v;
    atomicAdd(&denom[seg], v);
}

// ---------------- K5: weighted aggregation ----------------
__global__ void __launch_bounds__(256) agg_kernel(
    const float* __restrict__ vM, const float* __restrict__ ex, const float* __restrict__ denom,
    const int* __restrict__ src, const int* __restrict__ dst, const int* __restrict__ et,
    float* __restrict__ agg)
{
    int e = (blockIdx.x * blockDim.x + threadIdx.x) >> 5;
    if (e >= Ee) return;
    int lane = threadIdx.x & 31;
    int s = src[e], d = dst[e], r = et[e];
    float alpha = ex[e] / denom[d*Rr + r];
    const float4* vm = reinterpret_cast<const float4*>(vM + ((size_t)r*NP + s)*128);
    float4 v = vm[lane];
    float* out = agg + (size_t)d*128 + lane*4;
    asm volatile("red.global.add.v4.f32 [%0], {%1, %2, %3, %4};"
                 :: "l"(out), "f"(alpha*v.x), "f"(alpha*v.y), "f"(alpha*v.z), "f"(alpha*v.w)
                 : "memory");
}

// ---------------- K6: per-type output transform ----------------
__global__ void __launch_bounds__(256, 2) out_kernel(
    const float* __restrict__ agg, const float* __restrict__ aw,
    const float* __restrict__ skip, float* __restrict__ out)
{
    extern __shared__ char smem[];
    __shared__ int rows_s[128];

    int tid = threadIdx.x, wid = tid >> 5;
    int t = blockIdx.y;
    int base = g_off[t];
    int cnt = g_off[t+1] - base;
    int tb = blockIdx.x * 128;
    if (tb >= cnt) return;
    int mc = min(128, cnt - tb);

    if (tid < 128) rows_s[tid] = (tid < mc) ? g_bucket[base + tb + tid] : 0;
    __syncthreads();
    stage_A_gather(smem, agg, rows_s, mc, tid);

    FragC cf[8];
    #pragma unroll
    for (int nt = 0; nt < 8; nt++) wmma::fill_fragment(cf[nt], 0.f);

    int wrow0 = wid * 16;
    const float* W = aw + (size_t)t*16384;
    for (int ch = 0; ch < 2; ch++){
        __syncthreads();
        stage_B_split(smem, W, ch, tid);
        __syncthreads();
        mma_chunk(smem, cf, wrow0, ch);
    }

    float gate = 1.f / (1.f + __expf(-skip[t]));
    writeback_gather(smem, out, rows_s, mc, cf, wid, tid, gate);
}

// ---------------- launch ----------------
extern "C" void kernel_launch(void* const* d_in, const int* in_sizes, int n_in,
                              void* d_out, int out_size)
{
    const float* h     = (const float*)d_in[0];
    const int*   adj   = (const int*)d_in[1];
    const int*   etype = (const int*)d_in[2];
    const int*   ntype = (const int*)d_in[3];
    const float* kw    = (const float*)d_in[6];
    const float* qw    = (const float*)d_in[7];
    const float* vw    = (const float*)d_in[8];
    const float* aw    = (const float*)d_in[9];
    const float* pri   = (const float*)d_in[10];
    const float* att   = (const float*)d_in[11];
    const float* msg   = (const float*)d_in[12];
    const float* skip  = (const float*)d_in[13];
    const int* src = adj;
    const int* dst = adj + Ee;
    float* out = (float*)d_out;

    cudaFuncSetAttribute(proj_kqv_kernel, cudaFuncAttributeMaxDynamicSharedMemorySize, GEMM_SMEM);
    cudaFuncSetAttribute(relproj_kernel,  cudaFuncAttributeMaxDynamicSharedMemorySize, GEMM_SMEM);
    cudaFuncSetAttribute(out_kernel,      cudaFuncAttributeMaxDynamicSharedMemorySize, GEMM_SMEM);

    void *pk, *pq, *pv, *pkA, *pvM, *pscore, *pex, *psegmax, *pdenom, *pagg;
    cudaGetSymbolAddress(&pk, g_k);
    cudaGetSymbolAddress(&pq, g_q);
    cudaGetSymbolAddress(&pv, g_v);
    cudaGetSymbolAddress(&pkA, g_kA);
    cudaGetSymbolAddress(&pvM, g_vM);
    cudaGetSymbolAddress(&pscore, g_score);
    cudaGetSymbolAddress(&pex, g_ex);
    cudaGetSymbolAddress(&psegmax, g_segmax);
    cudaGetSymbolAddress(&pdenom, g_denom);
    cudaGetSymbolAddress(&pagg, g_agg);

    init_kernel<<<(Nn*128 + 255)/256, 256>>>();
    hist_kernel<<<(Nn + 255)/256, 256>>>(ntype);
    prefix_kernel<<<1, 32>>>();
    scatter_kernel<<<(Nn + 255)/256, 256>>>(ntype);
    zeropad_kernel<<<((NP - Nn)*128 + 255)/256, 256>>>((float*)pk, (float*)pv);

    dim3 gT((Nn + 127)/128, Tt);
    proj_kqv_kernel<<<gT, 256, GEMM_SMEM>>>(h, kw, qw, vw,
                                            (float*)pk, (float*)pq, (float*)pv);

    dim3 gR(NT, Rr, 2);
    relproj_kernel<<<gR, 256, GEMM_SMEM>>>((const float*)pk, (const float*)pv,
                                           att, msg, (float*)pkA, (float*)pvM);

    int score_blocks = (Ee + 7) / 8;
    score_kernel<<<score_blocks, 256>>>((const float*)pkA, (const float*)pq,
                                        src, dst, etype, pri,
                                        (float*)pscore, (unsigned*)psegmax);

    exp_kernel<<<(Ee + 255)/256, 256>>>((const float*)pscore, dst, etype,
                                        (const unsigned*)psegmax,
                                        (float*)pdenom, (float*)pex);

    agg_kernel<<<score_blocks, 256>>>((const float*)pvM, (const float*)pex,
                                      (const float*)pdenom, src, dst, etype,
                                      (float*)pagg);

    out_kernel<<<gT, 256, GEMM_SMEM>>>((const float*)pagg, aw, skip, out);
}